// round 16
// baseline (speedup 1.0000x reference)
#include <cuda_runtime.h>
#include <cuda_bf16.h>
#include <math.h>
#include <stdint.h>

#define TT 512
#define BB 64
#define HH 1024
#define G3 3072   // 3*H
#define LL 2
#define RB 128         // recurrence blocks, 1/SM, each owns 8 output columns j
#define WSTRIDE 1032   // W smem row stride (bf16 elem): 2064B -> 16B/row shift, conflict-free

// smem layout (bytes) for gru_rec_v8: packed W 48 rows | accbuf 48x66 fp32
#define OFF_WPK  0u
#define OFF_ACC  99072u                   // 48*2064
#define REC_SMEM (OFF_ACC + 48 * 66 * 4)  // 111744

// ---------------- scratch (static device arrays; no cudaMalloc) -------------
__device__ float g_xg[(size_t)TT * BB * G3];          // input gates, current layer
__device__ float g_y1[(size_t)TT * BB * HH];          // layer-1 output sequence
__device__ __nv_bfloat16 g_xhi[(size_t)TT * BB * HH]; // split X (hi)
__device__ __nv_bfloat16 g_xlo[(size_t)TT * BB * HH]; // split X (lo)
__device__ __nv_bfloat16 g_whi[(size_t)G3 * HH];      // split Wih (hi)
__device__ __nv_bfloat16 g_wlo[(size_t)G3 * HH];      // split Wih (lo)
__device__ __nv_bfloat16 g_vhi[(size_t)G3 * HH];      // split Whh (hi)
__device__ __nv_bfloat16 g_vlo[(size_t)G3 * HH];      // split Whh (lo)

// h in n8-granular B-fragment order:
// [buf][plane][(k16*8 + g8)*32 + lane] -> uint2 {k<8 pair-reg, k>=8 pair-reg}
__device__ uint2 g_hf2[2][2][64 * 8 * 32];

// 8 monotonic k-group publication counters (chunk c covers k in [c*128,(c+1)*128))
__device__ unsigned g_ctr[8];

// one-time init barrier state (flat atomic + generation: proven optimum)
__device__ unsigned g_bar_count = 0;
__device__ unsigned g_bar_gen   = 0;

// ======================= warp MMA helpers =====================================
__device__ __forceinline__ uint32_t smem_u32(const void* p) {
    uint32_t a;
    asm("{ .reg .u64 t; cvta.to.shared.u64 t, %1; cvt.u32.u64 %0, t; }"
        : "=r"(a) : "l"(p));
    return a;
}
__device__ __forceinline__ void ldmx4(uint32_t* r, uint32_t addr) {
    asm volatile("ldmatrix.sync.aligned.m8n8.x4.shared.b16 {%0,%1,%2,%3}, [%4];"
        : "=r"(r[0]), "=r"(r[1]), "=r"(r[2]), "=r"(r[3]) : "r"(addr));
}
__device__ __forceinline__ void mma16816(float* c, const uint32_t* a, const uint32_t* b) {
    asm volatile("mma.sync.aligned.m16n8k16.row.col.f32.bf16.bf16.f32 "
        "{%0,%1,%2,%3}, {%4,%5,%6,%7}, {%8,%9}, {%0,%1,%2,%3};"
        : "+f"(c[0]), "+f"(c[1]), "+f"(c[2]), "+f"(c[3])
        : "r"(a[0]), "r"(a[1]), "r"(a[2]), "r"(a[3]), "r"(b[0]), "r"(b[1]));
}

// ---------------- fp32 -> (hi, lo) bf16 split --------------------------------
__global__ void split_f32_kernel(const float* __restrict__ src,
                                 __nv_bfloat16* __restrict__ hi,
                                 __nv_bfloat16* __restrict__ lo, int n4)
{
    int i = blockIdx.x * blockDim.x + threadIdx.x;
    if (i >= n4) return;
    float4 v = ((const float4*)src)[i];
    float f[4] = {v.x, v.y, v.z, v.w};
    uint32_t ph[2], pl[2];
#pragma unroll
    for (int q = 0; q < 2; q++) {
        __nv_bfloat16 h0 = __float2bfloat16(f[q * 2 + 0]);
        __nv_bfloat16 h1 = __float2bfloat16(f[q * 2 + 1]);
        __nv_bfloat16 l0 = __float2bfloat16(f[q * 2 + 0] - __bfloat162float(h0));
        __nv_bfloat16 l1 = __float2bfloat16(f[q * 2 + 1] - __bfloat162float(h1));
        ph[q] = (uint32_t)__bfloat16_as_ushort(h0) | ((uint32_t)__bfloat16_as_ushort(h1) << 16);
        pl[q] = (uint32_t)__bfloat16_as_ushort(l0) | ((uint32_t)__bfloat16_as_ushort(l1) << 16);
    }
    ((uint2*)hi)[i] = make_uint2(ph[0], ph[1]);
    ((uint2*)lo)[i] = make_uint2(pl[0], pl[1]);
}

// ---------------- HMMA bf16-split input GEMM (validated, unchanged) -----------
#define SROW 72
__global__ void __launch_bounds__(256, 1)
gemm_xg_hmma(const __nv_bfloat16* __restrict__ Xhi, const __nv_bfloat16* __restrict__ Xlo,
             const __nv_bfloat16* __restrict__ Whi, const __nv_bfloat16* __restrict__ Wlo,
             const float* __restrict__ bias, float* __restrict__ C)
{
    extern __shared__ __nv_bfloat16 sm[];
    const int TILE = 128 * SROW;

    const int tid  = threadIdx.x;
    const int lane = tid & 31;
    const int wid  = tid >> 5;
    const int wm   = wid & 1;
    const int wn   = wid >> 1;
    const int n0   = blockIdx.x * 128;
    const int m0   = blockIdx.y * 128;

    const uint32_t smb = smem_u32(sm);

    float acc[4][4][4];
#pragma unroll
    for (int i = 0; i < 4; i++)
#pragma unroll
        for (int j = 0; j < 4; j++)
#pragma unroll
            for (int q = 0; q < 4; q++) acc[i][j][q] = 0.f;

    const int arow = (wm * 64 + (lane & 15)) * SROW + (lane >> 4) * 8;
    const int brow = (wn * 32 + (lane & 7) + ((lane >> 4) << 3)) * SROW
                   + ((lane >> 3) & 1) * 8;

    const __nv_bfloat16* srcs[4] = {
        Xhi + (size_t)m0 * HH, Xlo + (size_t)m0 * HH,
        Whi + (size_t)n0 * HH, Wlo + (size_t)n0 * HH };

    for (int ch = 0; ch < 16; ch++) {
        const int kt = ch * 64;
#pragma unroll
        for (int tile = 0; tile < 4; tile++) {
            const __nv_bfloat16* src = srcs[tile] + kt;
#pragma unroll
            for (int it = 0; it < 4; it++) {
                int idx = tid + it * 256;
                int row = idx >> 3, c8 = idx & 7;
                float4 v = *(const float4*)(src + (size_t)row * HH + c8 * 8);
                *(float4*)(sm + tile * TILE + row * SROW + c8 * 8) = v;
            }
        }
        __syncthreads();

#pragma unroll
        for (int ks = 0; ks < 4; ks++) {
            uint32_t ahi[4][4], alo[4][4], bhi[4][2], blo[4][2];
#pragma unroll
            for (int mf = 0; mf < 4; mf++) {
                uint32_t aoff = (uint32_t)(arow + mf * 16 * SROW + ks * 16) * 2;
                ldmx4(ahi[mf], smb + 0 * TILE * 2 + aoff);
                ldmx4(alo[mf], smb + 1 * TILE * 2 + aoff);
            }
#pragma unroll
            for (int pr = 0; pr < 2; pr++) {
                uint32_t boff = (uint32_t)(brow + pr * 16 * SROW + ks * 16) * 2;
                uint32_t rh[4], rl[4];
                ldmx4(rh, smb + 2 * TILE * 2 + boff);
                ldmx4(rl, smb + 3 * TILE * 2 + boff);
                bhi[pr * 2 + 0][0] = rh[0]; bhi[pr * 2 + 0][1] = rh[1];
                bhi[pr * 2 + 1][0] = rh[2]; bhi[pr * 2 + 1][1] = rh[3];
                blo[pr * 2 + 0][0] = rl[0]; blo[pr * 2 + 0][1] = rl[1];
                blo[pr * 2 + 1][0] = rl[2]; blo[pr * 2 + 1][1] = rl[3];
            }
#pragma unroll
            for (int mf = 0; mf < 4; mf++)
#pragma unroll
                for (int nf = 0; nf < 4; nf++) {
                    mma16816(acc[mf][nf], ahi[mf], bhi[nf]);
                    mma16816(acc[mf][nf], ahi[mf], blo[nf]);
                    mma16816(acc[mf][nf], alo[mf], bhi[nf]);
                }
        }
        __syncthreads();
    }

#pragma unroll
    for (int mf = 0; mf < 4; mf++) {
        int row = m0 + wm * 64 + mf * 16 + (lane >> 2);
#pragma unroll
        for (int nf = 0; nf < 4; nf++) {
            int col = n0 + wn * 32 + nf * 8 + (lane & 3) * 2;
            float b0 = bias[col], b1 = bias[col + 1];
            float2 v0 = make_float2(acc[mf][nf][0] + b0, acc[mf][nf][1] + b1);
            float2 v1 = make_float2(acc[mf][nf][2] + b0, acc[mf][nf][3] + b1);
            *(float2*)&C[(size_t)row * G3 + col]       = v0;
            *(float2*)&C[(size_t)(row + 8) * G3 + col] = v1;
        }
    }
}

// ---------------- one-time init grid barrier (flat atomic + gen) --------------
__device__ __forceinline__ void grid_bar_init()
{
    __threadfence();
    __syncthreads();
    if (threadIdx.x == 0) {
        unsigned gen = *(volatile unsigned*)&g_bar_gen;
        if (atomicAdd(&g_bar_count, 1u) == RB - 1) {
            g_bar_count = 0;
            __threadfence();
            *(volatile unsigned*)&g_bar_gen = gen + 1;
        } else {
            while (*(volatile unsigned*)&g_bar_gen == gen) __nanosleep(32);
        }
        __threadfence();
    }
    __syncthreads();
}

// ---------------- persistent GRU recurrence v8: chunked producer/consumer -----
// v7 arithmetic verbatim; the per-step global barrier is replaced by 8 monotonic
// k-group counters. Consumers (warps) poll ctr[c] >= 16*t before prefetching
// chunk c; producers publish once per step via one distributed atomicAdd.
__global__ void __launch_bounds__(256, 1)
gru_rec_v8(const float* __restrict__ h0,
           const __nv_bfloat16* __restrict__ vhi,
           const __nv_bfloat16* __restrict__ vlo,
           const float* __restrict__ bhh,
           const float* __restrict__ xg,     // [T,B,3H]
           float* __restrict__ Y,            // [T,B,H]
           float* __restrict__ hn)           // [B,H] or null
{
    extern __shared__ char smc[];
    float* accbuf      = (float*)(smc + OFF_ACC);    // [48 grow][66 batch]
    const uint32_t smb = smem_u32(smc);

    const int tid  = threadIdx.x;
    const int lane = tid & 31;
    const int g    = tid >> 5;               // warp = batch group (8 batches)
    const int bx   = blockIdx.x;
    const int j0   = bx * 8;
    const int grp  = bx >> 4;                // this block's k-group (publishes here)

    // ---- reset chunk counters (before the one-time init barrier) ----
    if (bx == 0 && tid < 8) g_ctr[tid] = 0;

    // ---- preload packed W: row p<24 = hi gate (p>>3) col j0+(p&7); p>=24 = lo --
    for (int i = tid; i < 48 * 128; i += 256) {
        int p = i >> 7, seg = i & 127;
        int pr = (p < 24) ? p : p - 24;
        const __nv_bfloat16* src = (p < 24) ? vhi : vlo;
        size_t off = ((size_t)(pr >> 3) * HH + j0 + (pr & 7)) * HH + seg * 8;
        *(uint4*)(smc + OFF_WPK + p * WSTRIDE * 2 + seg * 16) = *(const uint4*)(src + off);
    }

    // ---- per-thread ownership: (pb, j0+pj), (pb, j0+pj+1) ----
    const int pb = tid >> 2;
    const int pj = (tid & 3) * 2;
    const int j  = j0 + pj;
    const int fidx  = ((j >> 4) * 8 + (pb >> 3)) * 32 + (pb & 7) * 4 + ((j & 7) >> 1);
    const int fslot = (j >> 3) & 1;

    float hm0 = h0[(size_t)pb * HH + j];
    float hm1 = h0[(size_t)pb * HH + j + 1];
    {
        __nv_bfloat16 a = __float2bfloat16(hm0), b = __float2bfloat16(hm1);
        __nv_bfloat16 c = __float2bfloat16(hm0 - __bfloat162float(a));
        __nv_bfloat16 d = __float2bfloat16(hm1 - __bfloat162float(b));
        uint32_t ph = (uint32_t)__bfloat16_as_ushort(a) | ((uint32_t)__bfloat16_as_ushort(b) << 16);
        uint32_t pl = (uint32_t)__bfloat16_as_ushort(c) | ((uint32_t)__bfloat16_as_ushort(d) << 16);
        ((uint32_t*)&g_hf2[0][0][fidx])[fslot] = ph;
        ((uint32_t*)&g_hf2[0][1][fidx])[fslot] = pl;
    }
    const float br0 = bhh[j],          br1 = bhh[j + 1];
    const float bz0 = bhh[HH + j],     bz1 = bhh[HH + j + 1];
    const float bn0 = bhh[2 * HH + j], bn1 = bhh[2 * HH + j + 1];

    grid_bar_init();   // h(0) fragments + counter reset globally visible

    // A ldmatrix bases: tiles = rows 0-15, 16-31, 32-47
    const uint32_t a0 = (uint32_t)((lane & 15) * WSTRIDE + (lane >> 4) * 8) * 2;
    const uint32_t a1 = a0 + 16 * WSTRIDE * 2;
    const uint32_t a2 = a0 + 32 * WSTRIDE * 2;

    for (int t = 0; t < TT; t++) {
        const uint2* bufh = g_hf2[t & 1][0];
        const uint2* bufl = g_hf2[t & 1][1];
        const unsigned tgt = (unsigned)t * 16u;

        // xg prefetch (hidden behind the MMA loop)
        const float* xrow = xg + ((size_t)t * BB + pb) * G3;
        float2 xr = *(const float2*)&xrow[j];
        float2 xz = *(const float2*)&xrow[HH + j];
        float2 xn = *(const float2*)&xrow[2 * HH + j];

        float acc0[4] = {0.f, 0.f, 0.f, 0.f};
        float acc1[4] = {0.f, 0.f, 0.f, 0.f};
        float acc2[4] = {0.f, 0.f, 0.f, 0.f};

        // ---- wait for chunk 0 producers, then prologue load ----
        while (*(volatile unsigned*)&g_ctr[0] < tgt) __nanosleep(32);
        __threadfence();   // acquire: order data LDGs after the counter read
        uint2 Bh[2][8], Bl[2][8];
#pragma unroll
        for (int kk = 0; kk < 8; kk++) {
            Bh[0][kk] = __ldcg(&bufh[(kk * 8 + g) * 32 + lane]);
            Bl[0][kk] = __ldcg(&bufl[(kk * 8 + g) * 32 + lane]);
        }

        for (int c = 0; c < 8; c++) {
            const int cur = c & 1, nxt = cur ^ 1;
            if (c < 7) {
                while (*(volatile unsigned*)&g_ctr[c + 1] < tgt) __nanosleep(32);
                __threadfence();
                const int kb = (c + 1) * 8;
#pragma unroll
                for (int kk = 0; kk < 8; kk++) {
                    Bh[nxt][kk] = __ldcg(&bufh[((kb + kk) * 8 + g) * 32 + lane]);
                    Bl[nxt][kk] = __ldcg(&bufl[((kb + kk) * 8 + g) * 32 + lane]);
                }
            }
#pragma unroll
            for (int kk = 0; kk < 8; kk++) {
                const uint32_t koff = (uint32_t)(c * 8 + kk) * 32;
                uint32_t A0[4], A1[4], A2[4];
                ldmx4(A0, smb + OFF_WPK + a0 + koff);
                ldmx4(A1, smb + OFF_WPK + a1 + koff);
                ldmx4(A2, smb + OFF_WPK + a2 + koff);
                const uint32_t bh[2] = {Bh[cur][kk].x, Bh[cur][kk].y};
                const uint32_t bl[2] = {Bl[cur][kk].x, Bl[cur][kk].y};
                mma16816(acc0, A0, bh);
                mma16816(acc0, A0, bl);
                mma16816(acc1, A1, bh);
                mma16816(acc1, A1, bl);
                mma16816(acc2, A2, bh);
            }
        }

        // ---- accs -> accbuf (48 rows x 66) ----
        {
            int row = lane >> 2;
            int col = g * 8 + (lane & 3) * 2;
            accbuf[row * 66 + col]            = acc0[0];
            accbuf[row * 66 + col + 1]        = acc0[1];
            accbuf[(row + 8) * 66 + col]      = acc0[2];
            accbuf[(row + 8) * 66 + col + 1]  = acc0[3];
            accbuf[(row + 16) * 66 + col]     = acc1[0];
            accbuf[(row + 16) * 66 + col + 1] = acc1[1];
            accbuf[(row + 24) * 66 + col]     = acc1[2];
            accbuf[(row + 24) * 66 + col + 1] = acc1[3];
            accbuf[(row + 32) * 66 + col]     = acc2[0];
            accbuf[(row + 32) * 66 + col + 1] = acc2[1];
            accbuf[(row + 40) * 66 + col]     = acc2[2];
            accbuf[(row + 40) * 66 + col + 1] = acc2[3];
        }
        __syncthreads();

        // ---- pointwise GRU update: gate = hi_part + lo_part ----
        {
            float gr0 = accbuf[pj * 66 + pb]        + accbuf[(24 + pj) * 66 + pb];
            float gr1 = accbuf[(pj + 1) * 66 + pb]  + accbuf[(25 + pj) * 66 + pb];
            float gz0 = accbuf[(8 + pj) * 66 + pb]  + accbuf[(32 + pj) * 66 + pb];
            float gz1 = accbuf[(9 + pj) * 66 + pb]  + accbuf[(33 + pj) * 66 + pb];
            float gn0 = accbuf[(16 + pj) * 66 + pb] + accbuf[(40 + pj) * 66 + pb];
            float gn1 = accbuf[(17 + pj) * 66 + pb] + accbuf[(41 + pj) * 66 + pb];

            float r0 = 1.f / (1.f + expf(-(xr.x + gr0 + br0)));
            float r1 = 1.f / (1.f + expf(-(xr.y + gr1 + br1)));
            float z0 = 1.f / (1.f + expf(-(xz.x + gz0 + bz0)));
            float z1 = 1.f / (1.f + expf(-(xz.y + gz1 + bz1)));
            float n0 = tanhf(xn.x + r0 * (gn0 + bn0));
            float n1 = tanhf(xn.y + r1 * (gn1 + bn1));
            hm0 = (1.f - z0) * n0 + z0 * hm0;
            hm1 = (1.f - z1) * n1 + z1 * hm1;

            __nv_bfloat16 a = __float2bfloat16(hm0), b = __float2bfloat16(hm1);
            __nv_bfloat16 cc = __float2bfloat16(hm0 - __bfloat162float(a));
            __nv_bfloat16 dd = __float2bfloat16(hm1 - __bfloat162float(b));
            uint32_t ph = (uint32_t)__bfloat16_as_ushort(a) | ((uint32_t)__bfloat16_as_ushort(b) << 16);
            uint32_t pl = (uint32_t)__bfloat16_as_ushort(cc) | ((uint32_t)__bfloat16_as_ushort(dd) << 16);
            int nb = (t + 1) & 1;
            ((uint32_t*)&g_hf2[nb][0][fidx])[fslot] = ph;
            ((uint32_t*)&g_hf2[nb][1][fidx])[fslot] = pl;
            *(float2*)&Y[((size_t)t * BB + pb) * HH + j] = make_float2(hm0, hm1);
        }

        // ---- publish h(t+1): fence own stores, block-sync, one atomic ----
        __threadfence();
        __syncthreads();             // also covers accbuf WAR for next step
        if (tid == 0 && t < TT - 1)
            atomicAdd(&g_ctr[grp], 1u);
    }

    if (hn != nullptr)
        *(float2*)&hn[(size_t)pb * HH + j] = make_float2(hm0, hm1);
}

// ---------------- launch -------------------------------------------------------
extern "C" void kernel_launch(void* const* d_in, const int* in_sizes, int n_in,
                              void* d_out, int out_size)
{
    const float* x   = (const float*)d_in[0];
    const float* h0  = (const float*)d_in[1];
    const float* Wih = (const float*)d_in[2];
    const float* Whh = (const float*)d_in[3];
    const float* bih = (const float*)d_in[4];
    const float* bhh = (const float*)d_in[5];
    float* out = (float*)d_out;

    float *xg, *y1;
    __nv_bfloat16 *xhi, *xlo, *whi, *wlo, *vhi, *vlo;
    cudaGetSymbolAddress((void**)&xg,  g_xg);
    cudaGetSymbolAddress((void**)&y1,  g_y1);
    cudaGetSymbolAddress((void**)&xhi, g_xhi);
    cudaGetSymbolAddress((void**)&xlo, g_xlo);
    cudaGetSymbolAddress((void**)&whi, g_whi);
    cudaGetSymbolAddress((void**)&wlo, g_wlo);
    cudaGetSymbolAddress((void**)&vhi, g_vhi);
    cudaGetSymbolAddress((void**)&vlo, g_vlo);

    const int gemmSmem = 4 * 128 * SROW * 2;     // 73728 B
    static bool attr_set = false;
    if (!attr_set) {
        cudaFuncSetAttribute(gemm_xg_hmma,
                             cudaFuncAttributeMaxDynamicSharedMemorySize, gemmSmem);
        cudaFuncSetAttribute(gru_rec_v8,
                             cudaFuncAttributeMaxDynamicSharedMemorySize, REC_SMEM);
        attr_set = true;
    }

    const dim3 gemmGrid(G3 / 128, (TT * BB) / 128);   // 24 x 256
    const int  n4x = TT * BB * HH / 4;
    const int  n4w = G3 * HH / 4;
    const bool write_hn = (out_size >= TT * BB * HH + LL * BB * HH);

    for (int l = 0; l < LL; l++) {
        const float* Xin = (l == 0) ? x : y1;
        float* Y         = (l == 0) ? y1 : out;
        float* hn        = write_hn
            ? out + (size_t)TT * BB * HH + (size_t)l * BB * HH : nullptr;

        split_f32_kernel<<<(n4x + 255) / 256, 256>>>(Xin, xhi, xlo, n4x);
        split_f32_kernel<<<(n4w + 255) / 256, 256>>>(Wih + (size_t)l * G3 * HH,
                                                     whi, wlo, n4w);
        split_f32_kernel<<<(n4w + 255) / 256, 256>>>(Whh + (size_t)l * G3 * HH,
                                                     vhi, vlo, n4w);

        gemm_xg_hmma<<<gemmGrid, 256, gemmSmem>>>(xhi, xlo, whi, wlo,
                                                  bih + (size_t)l * G3, xg);

        gru_rec_v8<<<RB, 256, REC_SMEM>>>(h0 + (size_t)l * BB * HH,
                                          vhi, vlo, bhh + (size_t)l * G3,
                                          xg, Y, hn);
    }
}

// round 17
// speedup vs baseline: 1.3179x; 1.3179x over previous
#include <cuda_runtime.h>
#include <cuda_bf16.h>
#include <math.h>
#include <stdint.h>

#define TT 512
#define BB 64
#define HH 1024
#define G3 3072   // 3*H
#define LL 2
#define RB 128         // recurrence blocks, 1/SM, each owns 8 output columns j
#define WSTRIDE 1032   // W smem row stride (bf16 elem): 2064B -> 16B/row shift, conflict-free

// smem layout (bytes) for gru_rec_v9: packed W 48 rows | accbuf 48x66 fp32
#define OFF_WPK  0u
#define OFF_ACC  99072u                   // 48*2064
#define REC_SMEM (OFF_ACC + 48 * 66 * 4)  // 111744

// ---------------- scratch (static device arrays; no cudaMalloc) -------------
__device__ float g_xg[(size_t)TT * BB * G3];          // input gates, current layer
__device__ float g_y1[(size_t)TT * BB * HH];          // layer-1 output sequence
__device__ __nv_bfloat16 g_xhi[(size_t)TT * BB * HH]; // split X (hi)
__device__ __nv_bfloat16 g_xlo[(size_t)TT * BB * HH]; // split X (lo)
__device__ __nv_bfloat16 g_whi[(size_t)G3 * HH];      // split Wih (hi)
__device__ __nv_bfloat16 g_wlo[(size_t)G3 * HH];      // split Wih (lo)
__device__ __nv_bfloat16 g_vhi[(size_t)G3 * HH];      // split Whh (hi)
__device__ __nv_bfloat16 g_vlo[(size_t)G3 * HH];      // split Whh (lo)

// h in n8-granular B-fragment order, PAIRED k16 tiles (uint4):
// [buf][plane][(k32*8 + g8)*32 + lane] -> uint4
//   {x,y} = frag regs of k16 = 2*k32, {z,w} = frag regs of k16 = 2*k32+1
// writer u32 slot within uint4 = (j>>3)&3; lane = (pb&7)*4 + ((j&7)>>1)
__device__ uint4 g_hf4[2][2][32 * 8 * 32];

// grid-barrier state (flat atomic + generation: proven optimum of 4 variants)
__device__ unsigned g_bar_count = 0;
__device__ unsigned g_bar_gen   = 0;

// ======================= warp MMA helpers =====================================
__device__ __forceinline__ uint32_t smem_u32(const void* p) {
    uint32_t a;
    asm("{ .reg .u64 t; cvta.to.shared.u64 t, %1; cvt.u32.u64 %0, t; }"
        : "=r"(a) : "l"(p));
    return a;
}
__device__ __forceinline__ void ldmx4(uint32_t* r, uint32_t addr) {
    asm volatile("ldmatrix.sync.aligned.m8n8.x4.shared.b16 {%0,%1,%2,%3}, [%4];"
        : "=r"(r[0]), "=r"(r[1]), "=r"(r[2]), "=r"(r[3]) : "r"(addr));
}
__device__ __forceinline__ void mma16816(float* c, const uint32_t* a, const uint32_t* b) {
    asm volatile("mma.sync.aligned.m16n8k16.row.col.f32.bf16.bf16.f32 "
        "{%0,%1,%2,%3}, {%4,%5,%6,%7}, {%8,%9}, {%0,%1,%2,%3};"
        : "+f"(c[0]), "+f"(c[1]), "+f"(c[2]), "+f"(c[3])
        : "r"(a[0]), "r"(a[1]), "r"(a[2]), "r"(a[3]), "r"(b[0]), "r"(b[1]));
}
#define CP_ASYNC16(dst, src) \
    asm volatile("cp.async.cg.shared.global [%0], [%1], 16;" :: "r"(dst), "l"(src))
#define CP_COMMIT   asm volatile("cp.async.commit_group;" ::: "memory")
#define CP_WAIT0    asm volatile("cp.async.wait_group 0;" ::: "memory")

// ---------------- fp32 -> (hi, lo) bf16 split --------------------------------
__global__ void split_f32_kernel(const float* __restrict__ src,
                                 __nv_bfloat16* __restrict__ hi,
                                 __nv_bfloat16* __restrict__ lo, int n4)
{
    int i = blockIdx.x * blockDim.x + threadIdx.x;
    if (i >= n4) return;
    float4 v = ((const float4*)src)[i];
    float f[4] = {v.x, v.y, v.z, v.w};
    uint32_t ph[2], pl[2];
#pragma unroll
    for (int q = 0; q < 2; q++) {
        __nv_bfloat16 h0 = __float2bfloat16(f[q * 2 + 0]);
        __nv_bfloat16 h1 = __float2bfloat16(f[q * 2 + 1]);
        __nv_bfloat16 l0 = __float2bfloat16(f[q * 2 + 0] - __bfloat162float(h0));
        __nv_bfloat16 l1 = __float2bfloat16(f[q * 2 + 1] - __bfloat162float(h1));
        ph[q] = (uint32_t)__bfloat16_as_ushort(h0) | ((uint32_t)__bfloat16_as_ushort(h1) << 16);
        pl[q] = (uint32_t)__bfloat16_as_ushort(l0) | ((uint32_t)__bfloat16_as_ushort(l1) << 16);
    }
    ((uint2*)hi)[i] = make_uint2(ph[0], ph[1]);
    ((uint2*)lo)[i] = make_uint2(pl[0], pl[1]);
}

// ---------------- HMMA bf16-split input GEMM, cp.async double-buffered --------
#define SROW 72
#define GTILE (128 * SROW)          // elements per operand tile
#define GBUF  (4 * GTILE * 2)       // bytes per smem buffer (73728)
__global__ void __launch_bounds__(256, 1)
gemm_xg_hmma(const __nv_bfloat16* __restrict__ Xhi, const __nv_bfloat16* __restrict__ Xlo,
             const __nv_bfloat16* __restrict__ Whi, const __nv_bfloat16* __restrict__ Wlo,
             const float* __restrict__ bias, float* __restrict__ C)
{
    extern __shared__ __nv_bfloat16 sm[];

    const int tid  = threadIdx.x;
    const int lane = tid & 31;
    const int wid  = tid >> 5;
    const int wm   = wid & 1;
    const int wn   = wid >> 1;
    const int n0   = blockIdx.x * 128;
    const int m0   = blockIdx.y * 128;

    const uint32_t smb = smem_u32(sm);

    float acc[4][4][4];
#pragma unroll
    for (int i = 0; i < 4; i++)
#pragma unroll
        for (int j = 0; j < 4; j++)
#pragma unroll
            for (int q = 0; q < 4; q++) acc[i][j][q] = 0.f;

    const int arow = (wm * 64 + (lane & 15)) * SROW + (lane >> 4) * 8;
    const int brow = (wn * 32 + (lane & 7) + ((lane >> 4) << 3)) * SROW
                   + ((lane >> 3) & 1) * 8;

    const __nv_bfloat16* srcs[4] = {
        Xhi + (size_t)m0 * HH, Xlo + (size_t)m0 * HH,
        Whi + (size_t)n0 * HH, Wlo + (size_t)n0 * HH };

    // stage chunk ch into buffer buf (4 tiles x 128 rows x 64 bf16, cp.async)
    auto stage = [&](int ch, int buf) {
        const int kt = ch * 64;
        const uint32_t bb = smb + (uint32_t)buf * GBUF;
#pragma unroll
        for (int tile = 0; tile < 4; tile++) {
            const __nv_bfloat16* src = srcs[tile] + kt;
#pragma unroll
            for (int it = 0; it < 4; it++) {
                int idx = tid + it * 256;
                int row = idx >> 3, c8 = idx & 7;
                CP_ASYNC16(bb + (uint32_t)(tile * GTILE + row * SROW + c8 * 8) * 2,
                           src + (size_t)row * HH + c8 * 8);
            }
        }
        CP_COMMIT;
    };

    stage(0, 0);

    for (int ch = 0; ch < 16; ch++) {
        CP_WAIT0;            // chunk ch resident
        __syncthreads();     // also: all MMA-reads of the other buffer are done
        if (ch + 1 < 16) stage(ch + 1, (ch + 1) & 1);   // overlaps MMAs below

        const uint32_t bb = smb + (uint32_t)(ch & 1) * GBUF;
#pragma unroll
        for (int ks = 0; ks < 4; ks++) {
            uint32_t ahi[4][4], alo[4][4], bhi[4][2], blo[4][2];
#pragma unroll
            for (int mf = 0; mf < 4; mf++) {
                uint32_t aoff = (uint32_t)(arow + mf * 16 * SROW + ks * 16) * 2;
                ldmx4(ahi[mf], bb + 0 * GTILE * 2 + aoff);
                ldmx4(alo[mf], bb + 1 * GTILE * 2 + aoff);
            }
#pragma unroll
            for (int pr = 0; pr < 2; pr++) {
                uint32_t boff = (uint32_t)(brow + pr * 16 * SROW + ks * 16) * 2;
                uint32_t rh[4], rl[4];
                ldmx4(rh, bb + 2 * GTILE * 2 + boff);
                ldmx4(rl, bb + 3 * GTILE * 2 + boff);
                bhi[pr * 2 + 0][0] = rh[0]; bhi[pr * 2 + 0][1] = rh[1];
                bhi[pr * 2 + 1][0] = rh[2]; bhi[pr * 2 + 1][1] = rh[3];
                blo[pr * 2 + 0][0] = rl[0]; blo[pr * 2 + 0][1] = rl[1];
                blo[pr * 2 + 1][0] = rl[2]; blo[pr * 2 + 1][1] = rl[3];
            }
#pragma unroll
            for (int mf = 0; mf < 4; mf++)
#pragma unroll
                for (int nf = 0; nf < 4; nf++) {
                    mma16816(acc[mf][nf], ahi[mf], bhi[nf]);
                    mma16816(acc[mf][nf], ahi[mf], blo[nf]);
                    mma16816(acc[mf][nf], alo[mf], bhi[nf]);
                }
        }
        __syncthreads();     // reads of buf ch&1 complete before it is restaged
    }

#pragma unroll
    for (int mf = 0; mf < 4; mf++) {
        int row = m0 + wm * 64 + mf * 16 + (lane >> 2);
#pragma unroll
        for (int nf = 0; nf < 4; nf++) {
            int col = n0 + wn * 32 + nf * 8 + (lane & 3) * 2;
            float b0 = bias[col], b1 = bias[col + 1];
            float2 v0 = make_float2(acc[mf][nf][0] + b0, acc[mf][nf][1] + b1);
            float2 v1 = make_float2(acc[mf][nf][2] + b0, acc[mf][nf][3] + b1);
            *(float2*)&C[(size_t)row * G3 + col]       = v0;
            *(float2*)&C[(size_t)(row + 8) * G3 + col] = v1;
        }
    }
}

// ---------------- software grid barrier (flat atomic + gen; proven fast) ------
__device__ __forceinline__ void grid_bar()
{
    __threadfence();
    __syncthreads();
    if (threadIdx.x == 0) {
        unsigned gen = *(volatile unsigned*)&g_bar_gen;
        if (atomicAdd(&g_bar_count, 1u) == RB - 1) {
            g_bar_count = 0;
            __threadfence();
            *(volatile unsigned*)&g_bar_gen = gen + 1;
        } else {
            while (*(volatile unsigned*)&g_bar_gen == gen) __nanosleep(32);
        }
        __threadfence();
    }
    __syncthreads();
}

// ---------------- persistent GRU recurrence v9 = v7 + uint4 h fragments -------
// Identical arithmetic/sync to v7 (champion); only the h-fragment container is
// widened to uint4 (paired k16 tiles) -> half the B-side LDG instructions.
__global__ void __launch_bounds__(256, 1)
gru_rec_v9(const float* __restrict__ h0,
           const __nv_bfloat16* __restrict__ vhi,
           const __nv_bfloat16* __restrict__ vlo,
           const float* __restrict__ bhh,
           const float* __restrict__ xg,     // [T,B,3H]
           float* __restrict__ Y,            // [T,B,H]
           float* __restrict__ hn)           // [B,H] or null
{
    extern __shared__ char smc[];
    float* accbuf      = (float*)(smc + OFF_ACC);    // [48 grow][66 batch]
    const uint32_t smb = smem_u32(smc);

    const int tid  = threadIdx.x;
    const int lane = tid & 31;
    const int g    = tid >> 5;               // warp = batch group (8 batches)
    const int j0   = blockIdx.x * 8;

    // ---- preload packed W: row p<24 = hi gate (p>>3) col j0+(p&7); p>=24 = lo --
    for (int i = tid; i < 48 * 128; i += 256) {
        int p = i >> 7, seg = i & 127;
        int pr = (p < 24) ? p : p - 24;
        const __nv_bfloat16* src = (p < 24) ? vhi : vlo;
        size_t off = ((size_t)(pr >> 3) * HH + j0 + (pr & 7)) * HH + seg * 8;
        *(uint4*)(smc + OFF_WPK + p * WSTRIDE * 2 + seg * 16) = *(const uint4*)(src + off);
    }

    // ---- per-thread ownership: (pb, j0+pj), (pb, j0+pj+1) ----
    const int pb = tid >> 2;
    const int pj = (tid & 3) * 2;
    const int j  = j0 + pj;
    // uint4 fragment write coordinates
    const int fidx  = ((j >> 5) * 8 + (pb >> 3)) * 32 + (pb & 7) * 4 + ((j & 7) >> 1);
    const int fslot = (j >> 3) & 3;

    float hm0 = h0[(size_t)pb * HH + j];
    float hm1 = h0[(size_t)pb * HH + j + 1];
    {
        __nv_bfloat16 a = __float2bfloat16(hm0), b = __float2bfloat16(hm1);
        __nv_bfloat16 c = __float2bfloat16(hm0 - __bfloat162float(a));
        __nv_bfloat16 d = __float2bfloat16(hm1 - __bfloat162float(b));
        uint32_t ph = (uint32_t)__bfloat16_as_ushort(a) | ((uint32_t)__bfloat16_as_ushort(b) << 16);
        uint32_t pl = (uint32_t)__bfloat16_as_ushort(c) | ((uint32_t)__bfloat16_as_ushort(d) << 16);
        ((uint32_t*)&g_hf4[0][0][fidx])[fslot] = ph;
        ((uint32_t*)&g_hf4[0][1][fidx])[fslot] = pl;
    }
    const float br0 = bhh[j],          br1 = bhh[j + 1];
    const float bz0 = bhh[HH + j],     bz1 = bhh[HH + j + 1];
    const float bn0 = bhh[2 * HH + j], bn1 = bhh[2 * HH + j + 1];

    grid_bar();

    // A ldmatrix bases: tiles = rows 0-15, 16-31, 32-47
    const uint32_t a0 = (uint32_t)((lane & 15) * WSTRIDE + (lane >> 4) * 8) * 2;
    const uint32_t a1 = a0 + 16 * WSTRIDE * 2;
    const uint32_t a2 = a0 + 32 * WSTRIDE * 2;

    for (int t = 0; t < TT; t++) {
        const uint4* bufh = g_hf4[t & 1][0];
        const uint4* bufl = g_hf4[t & 1][1];

        // xg prefetch (hidden behind the MMA loop)
        const float* xrow = xg + ((size_t)t * BB + pb) * G3;
        float2 xr = *(const float2*)&xrow[j];
        float2 xz = *(const float2*)&xrow[HH + j];
        float2 xn = *(const float2*)&xrow[2 * HH + j];

        float acc0[4] = {0.f, 0.f, 0.f, 0.f};
        float acc1[4] = {0.f, 0.f, 0.f, 0.f};
        float acc2[4] = {0.f, 0.f, 0.f, 0.f};

        // chunk-level double-buffered B fragments: 4 uint4 = 8 k16 per chunk
        uint4 Bh[2][4], Bl[2][4];
#pragma unroll
        for (int q = 0; q < 4; q++) {
            Bh[0][q] = __ldcg(&bufh[(q * 8 + g) * 32 + lane]);
            Bl[0][q] = __ldcg(&bufl[(q * 8 + g) * 32 + lane]);
        }

        for (int c = 0; c < 8; c++) {
            const int cur = c & 1, nxt = cur ^ 1;
            if (c < 7) {
                const int qb = (c + 1) * 4;
#pragma unroll
                for (int q = 0; q < 4; q++) {
                    Bh[nxt][q] = __ldcg(&bufh[((qb + q) * 8 + g) * 32 + lane]);
                    Bl[nxt][q] = __ldcg(&bufl[((qb + q) * 8 + g) * 32 + lane]);
                }
            }
#pragma unroll
            for (int kk = 0; kk < 8; kk++) {
                const uint32_t koff = (uint32_t)(c * 8 + kk) * 32;
                uint32_t A0[4], A1[4], A2[4];
                ldmx4(A0, smb + OFF_WPK + a0 + koff);
                ldmx4(A1, smb + OFF_WPK + a1 + koff);
                ldmx4(A2, smb + OFF_WPK + a2 + koff);
                const uint4& h4 = Bh[cur][kk >> 1];
                const uint4& l4 = Bl[cur][kk >> 1];
                const uint32_t bh[2] = {(kk & 1) ? h4.z : h4.x, (kk & 1) ? h4.w : h4.y};
                const uint32_t bl[2] = {(kk & 1) ? l4.z : l4.x, (kk & 1) ? l4.w : l4.y};
                mma16816(acc0, A0, bh);
                mma16816(acc0, A0, bl);
                mma16816(acc1, A1, bh);
                mma16816(acc1, A1, bl);
                mma16816(acc2, A2, bh);
            }
        }

        // ---- accs -> accbuf (48 rows x 66) ----
        {
            int row = lane >> 2;
            int col = g * 8 + (lane & 3) * 2;
            accbuf[row * 66 + col]            = acc0[0];
            accbuf[row * 66 + col + 1]        = acc0[1];
            accbuf[(row + 8) * 66 + col]      = acc0[2];
            accbuf[(row + 8) * 66 + col + 1]  = acc0[3];
            accbuf[(row + 16) * 66 + col]     = acc1[0];
            accbuf[(row + 16) * 66 + col + 1] = acc1[1];
            accbuf[(row + 24) * 66 + col]     = acc1[2];
            accbuf[(row + 24) * 66 + col + 1] = acc1[3];
            accbuf[(row + 32) * 66 + col]     = acc2[0];
            accbuf[(row + 32) * 66 + col + 1] = acc2[1];
            accbuf[(row + 40) * 66 + col]     = acc2[2];
            accbuf[(row + 40) * 66 + col + 1] = acc2[3];
        }
        __syncthreads();

        // ---- pointwise GRU update: gate = hi_part + lo_part ----
        {
            float gr0 = accbuf[pj * 66 + pb]        + accbuf[(24 + pj) * 66 + pb];
            float gr1 = accbuf[(pj + 1) * 66 + pb]  + accbuf[(25 + pj) * 66 + pb];
            float gz0 = accbuf[(8 + pj) * 66 + pb]  + accbuf[(32 + pj) * 66 + pb];
            float gz1 = accbuf[(9 + pj) * 66 + pb]  + accbuf[(33 + pj) * 66 + pb];
            float gn0 = accbuf[(16 + pj) * 66 + pb] + accbuf[(40 + pj) * 66 + pb];
            float gn1 = accbuf[(17 + pj) * 66 + pb] + accbuf[(41 + pj) * 66 + pb];

            float r0 = 1.f / (1.f + expf(-(xr.x + gr0 + br0)));
            float r1 = 1.f / (1.f + expf(-(xr.y + gr1 + br1)));
            float z0 = 1.f / (1.f + expf(-(xz.x + gz0 + bz0)));
            float z1 = 1.f / (1.f + expf(-(xz.y + gz1 + bz1)));
            float n0 = tanhf(xn.x + r0 * (gn0 + bn0));
            float n1 = tanhf(xn.y + r1 * (gn1 + bn1));
            hm0 = (1.f - z0) * n0 + z0 * hm0;
            hm1 = (1.f - z1) * n1 + z1 * hm1;

            __nv_bfloat16 a = __float2bfloat16(hm0), b = __float2bfloat16(hm1);
            __nv_bfloat16 cc = __float2bfloat16(hm0 - __bfloat162float(a));
            __nv_bfloat16 dd = __float2bfloat16(hm1 - __bfloat162float(b));
            uint32_t ph = (uint32_t)__bfloat16_as_ushort(a) | ((uint32_t)__bfloat16_as_ushort(b) << 16);
            uint32_t pl = (uint32_t)__bfloat16_as_ushort(cc) | ((uint32_t)__bfloat16_as_ushort(dd) << 16);
            int nb = (t + 1) & 1;
            ((uint32_t*)&g_hf4[nb][0][fidx])[fslot] = ph;
            ((uint32_t*)&g_hf4[nb][1][fidx])[fslot] = pl;
            *(float2*)&Y[((size_t)t * BB + pb) * HH + j] = make_float2(hm0, hm1);
        }

        if (t < TT - 1) grid_bar();
    }

    if (hn != nullptr)
        *(float2*)&hn[(size_t)pb * HH + j] = make_float2(hm0, hm1);
}

// ---------------- launch -------------------------------------------------------
extern "C" void kernel_launch(void* const* d_in, const int* in_sizes, int n_in,
                              void* d_out, int out_size)
{
    const float* x   = (const float*)d_in[0];
    const float* h0  = (const float*)d_in[1];
    const float* Wih = (const float*)d_in[2];
    const float* Whh = (const float*)d_in[3];
    const float* bih = (const float*)d_in[4];
    const float* bhh = (const float*)d_in[5];
    float* out = (float*)d_out;

    float *xg, *y1;
    __nv_bfloat16 *xhi, *xlo, *whi, *wlo, *vhi, *vlo;
    cudaGetSymbolAddress((void**)&xg,  g_xg);
    cudaGetSymbolAddress((void**)&y1,  g_y1);
    cudaGetSymbolAddress((void**)&xhi, g_xhi);
    cudaGetSymbolAddress((void**)&xlo, g_xlo);
    cudaGetSymbolAddress((void**)&whi, g_whi);
    cudaGetSymbolAddress((void**)&wlo, g_wlo);
    cudaGetSymbolAddress((void**)&vhi, g_vhi);
    cudaGetSymbolAddress((void**)&vlo, g_vlo);

    const int gemmSmem = 2 * GBUF;               // 147456 B (double-buffered)
    static bool attr_set = false;
    if (!attr_set) {
        cudaFuncSetAttribute(gemm_xg_hmma,
                             cudaFuncAttributeMaxDynamicSharedMemorySize, gemmSmem);
        cudaFuncSetAttribute(gru_rec_v9,
                             cudaFuncAttributeMaxDynamicSharedMemorySize, REC_SMEM);
        attr_set = true;
    }

    const dim3 gemmGrid(G3 / 128, (TT * BB) / 128);   // 24 x 256
    const int  n4x = TT * BB * HH / 4;
    const int  n4w = G3 * HH / 4;
    const bool write_hn = (out_size >= TT * BB * HH + LL * BB * HH);

    for (int l = 0; l < LL; l++) {
        const float* Xin = (l == 0) ? x : y1;
        float* Y         = (l == 0) ? y1 : out;
        float* hn        = write_hn
            ? out + (size_t)TT * BB * HH + (size_t)l * BB * HH : nullptr;

        split_f32_kernel<<<(n4x + 255) / 256, 256>>>(Xin, xhi, xlo, n4x);
        split_f32_kernel<<<(n4w + 255) / 256, 256>>>(Wih + (size_t)l * G3 * HH,
                                                     whi, wlo, n4w);
        split_f32_kernel<<<(n4w + 255) / 256, 256>>>(Whh + (size_t)l * G3 * HH,
                                                     vhi, vlo, n4w);

        gemm_xg_hmma<<<gemmGrid, 256, gemmSmem>>>(xhi, xlo, whi, wlo,
                                                  bih + (size_t)l * G3, xg);

        gru_rec_v9<<<RB, 256, REC_SMEM>>>(h0 + (size_t)l * BB * HH,
                                          vhi, vlo, bhh + (size_t)l * G3,
                                          xg, Y, hn);
    }
}